// round 1
// baseline (speedup 1.0000x reference)
#include <cuda_runtime.h>
#include <math.h>

#define S_TOTAL 15768
#define NQ 300
#define C_MODEL 256
#define NHEADS 8
#define DHEAD 32
#define NLAYERS 6
#define DFF 1024
#define MASK_N (NQ * S_TOTAL)

// ------------------------- scratch (device globals) -------------------------
__device__ float g_srct[S_TOTAL * C_MODEL];     // src transposed [S, C]
__device__ float g_srcpos[S_TOTAL * C_MODEL];   // (src+pos) transposed [S, C]
__device__ float g_maskbias[MASK_N];            // 0 or -1e30
__device__ float g_Kbuf[S_TOTAL * C_MODEL];
__device__ float g_Vbuf[S_TOTAL * C_MODEL];
__device__ float g_cascores[(size_t)NHEADS * NQ * S_TOTAL];   // ~151 MB
__device__ float g_sascores[NHEADS * NQ * NQ];
__device__ float g_x[NQ * C_MODEL];
__device__ float g_qe[NQ * C_MODEL];
__device__ float g_t1[NQ * C_MODEL];
__device__ float g_t2[NQ * C_MODEL];
__device__ float g_qb[NQ * C_MODEL];
__device__ float g_kb[NQ * C_MODEL];
__device__ float g_vb[NQ * C_MODEL];
__device__ float g_ao[NQ * C_MODEL];
__device__ float g_ffh[NQ * DFF];
__device__ int   g_mask_float;
__device__ int   g_mask_byte;

// ------------------------- kernels -------------------------

// C[M,N] = alpha * (A[M,K] @ B[N,K]^T + bias[N]) + add[M,N]; optional relu.
// Batched over blockIdx.z with strides sA/sB/sC (add is shared across batch).
__global__ __launch_bounds__(256) void gemm_tn(
    const float* __restrict__ A, const float* __restrict__ B,
    const float* __restrict__ bias, const float* __restrict__ add,
    float* __restrict__ C,
    int M, int N, int K, int lda, int ldb, int ldc, int ldadd,
    long sA, long sB, long sC, float alpha, int relu)
{
    __shared__ float As[16][65];
    __shared__ float Bs[16][65];
    int b = blockIdx.z;
    A += (long)b * sA; B += (long)b * sB; C += (long)b * sC;
    int m0 = blockIdx.y * 64, n0 = blockIdx.x * 64;
    int tid = threadIdx.x;
    int tn = tid & 15, tm = tid >> 4;
    float acc[4][4] = {};
    for (int k0 = 0; k0 < K; k0 += 16) {
        #pragma unroll
        for (int i = 0; i < 4; i++) {
            int idx = tid + i * 256;
            int r = idx >> 4, k = idx & 15;
            float va = 0.f, vb = 0.f;
            if (m0 + r < M && k0 + k < K) va = A[(long)(m0 + r) * lda + k0 + k];
            if (n0 + r < N && k0 + k < K) vb = B[(long)(n0 + r) * ldb + k0 + k];
            As[k][r] = va;
            Bs[k][r] = vb;
        }
        __syncthreads();
        #pragma unroll
        for (int k = 0; k < 16; k++) {
            float a[4], bb[4];
            #pragma unroll
            for (int i = 0; i < 4; i++) a[i] = As[k][tm * 4 + i];
            #pragma unroll
            for (int j = 0; j < 4; j++) bb[j] = Bs[k][tn * 4 + j];
            #pragma unroll
            for (int i = 0; i < 4; i++)
                #pragma unroll
                for (int j = 0; j < 4; j++)
                    acc[i][j] += a[i] * bb[j];
        }
        __syncthreads();
    }
    #pragma unroll
    for (int i = 0; i < 4; i++) {
        int m = m0 + tm * 4 + i;
        if (m >= M) continue;
        #pragma unroll
        for (int j = 0; j < 4; j++) {
            int n = n0 + tn * 4 + j;
            if (n >= N) continue;
            float v = acc[i][j];
            if (bias) v += bias[n];
            v *= alpha;
            if (add) v += add[(long)m * ldadd + n];
            if (relu) v = fmaxf(v, 0.f);
            C[(long)m * ldc + n] = v;
        }
    }
}

// C[M,N] = A[M,K] @ B[K,N], batched over blockIdx.z.
__global__ __launch_bounds__(256) void gemm_nn(
    const float* __restrict__ A, const float* __restrict__ B,
    float* __restrict__ C,
    int M, int N, int K, int lda, int ldb, int ldc,
    long sA, long sB, long sC)
{
    __shared__ float As[32][33];
    __shared__ float Bs[32][33];
    int b = blockIdx.z;
    A += (long)b * sA; B += (long)b * sB; C += (long)b * sC;
    int m0 = blockIdx.y * 32, n0 = blockIdx.x * 32;
    int tid = threadIdx.x;
    int tx = tid & 31, ty = tid >> 5;  // ty in 0..7
    float acc[4] = {};
    for (int k0 = 0; k0 < K; k0 += 32) {
        #pragma unroll
        for (int i = 0; i < 4; i++) {
            int idx = tid + i * 256;
            int r = idx >> 5, cc = idx & 31;
            float va = 0.f, vb = 0.f;
            if (m0 + r < M && k0 + cc < K) va = A[(long)(m0 + r) * lda + k0 + cc];
            if (k0 + r < K && n0 + cc < N) vb = B[(long)(k0 + r) * ldb + n0 + cc];
            As[r][cc] = va;
            Bs[r][cc] = vb;
        }
        __syncthreads();
        #pragma unroll
        for (int k = 0; k < 32; k++) {
            float bv = Bs[k][tx];
            #pragma unroll
            for (int i = 0; i < 4; i++)
                acc[i] += As[ty + i * 8][k] * bv;
        }
        __syncthreads();
    }
    #pragma unroll
    for (int i = 0; i < 4; i++) {
        int m = m0 + ty + i * 8;
        int n = n0 + tx;
        if (m < M && n < N) C[(long)m * ldc + n] = acc[i];
    }
}

// In-place softmax over rows of length rowlen. One block (256 thr) per row.
__global__ __launch_bounds__(256) void softmax_rows(float* __restrict__ P, int rowlen)
{
    long r = blockIdx.x;
    float* p = P + r * (long)rowlen;
    int tid = threadIdx.x;
    float m = -3.4e38f, s = 0.f;
    for (int i = tid; i < rowlen; i += 256) {
        float x = p[i];
        if (x > m) { s = s * expf(m - x) + 1.f; m = x; }
        else       { s += expf(x - m); }
    }
    __shared__ float sm[256], ss[256];
    sm[tid] = m; ss[tid] = s;
    __syncthreads();
    for (int off = 128; off > 0; off >>= 1) {
        if (tid < off) {
            float m1 = sm[tid], m2 = sm[tid + off];
            float s1 = ss[tid], s2 = ss[tid + off];
            float mm = fmaxf(m1, m2);
            sm[tid] = mm;
            ss[tid] = s1 * expf(m1 - mm) + s2 * expf(m2 - mm);
        }
        __syncthreads();
    }
    float Mx = sm[0];
    float inv = 1.f / ss[0];
    for (int i = tid; i < rowlen; i += 256)
        p[i] = expf(p[i] - Mx) * inv;
}

// x[r,:] = LN(x[r,:] + res[r,:]) * w + b    (C=256, one block/row, 256 thr)
__global__ __launch_bounds__(256) void residual_ln(
    float* __restrict__ x, const float* __restrict__ res,
    const float* __restrict__ w, const float* __restrict__ b)
{
    int r = blockIdx.x;
    int c = threadIdx.x;
    float v = x[r * 256 + c] + res[r * 256 + c];
    __shared__ float red[256];
    red[c] = v; __syncthreads();
    for (int off = 128; off > 0; off >>= 1) { if (c < off) red[c] += red[c + off]; __syncthreads(); }
    float mean = red[0] * (1.f / 256.f);
    __syncthreads();
    float d = v - mean;
    red[c] = d * d; __syncthreads();
    for (int off = 128; off > 0; off >>= 1) { if (c < off) red[c] += red[c + off]; __syncthreads(); }
    float var = red[0] * (1.f / 256.f);
    x[r * 256 + c] = d * rsqrtf(var + 1e-5f) * w[c] + b[c];
}

__global__ void add_vec(const float* a, const float* b, float* c, int n)
{
    int i = blockIdx.x * 256 + threadIdx.x;
    if (i < n) c[i] = a[i] + b[i];
}

// transpose srcs [C,S] -> srct [S,C]; srcpos = srcs+pos transposed
__global__ void prep_src(const float* __restrict__ srcs, const float* __restrict__ pos,
                         float* __restrict__ srct, float* __restrict__ srcpos)
{
    __shared__ float t1[32][33], t2[32][33];
    int s0 = blockIdx.x * 32, c0 = blockIdx.y * 32;
    int tx = threadIdx.x, ty = threadIdx.y;  // (32,8)
    #pragma unroll
    for (int i = 0; i < 4; i++) {
        int c = c0 + ty + i * 8, s = s0 + tx;
        float a = 0.f, f = 0.f;
        if (s < S_TOTAL) { a = srcs[(long)c * S_TOTAL + s]; f = pos[(long)c * S_TOTAL + s]; }
        t1[ty + i * 8][tx] = a;
        t2[ty + i * 8][tx] = f;
    }
    __syncthreads();
    #pragma unroll
    for (int i = 0; i < 4; i++) {
        int s = s0 + ty + i * 8, c = c0 + tx;
        if (s < S_TOTAL) {
            float a = t1[tx][ty + i * 8];
            float f = t2[tx][ty + i * 8];
            srct[(long)s * 256 + c]   = a;
            srcpos[(long)s * 256 + c] = a + f;
        }
    }
}

__global__ void init_qx(const float* __restrict__ qemb, float* __restrict__ qe, float* __restrict__ x)
{
    int r = blockIdx.x, c = threadIdx.x;
    qe[r * 256 + c] = qemb[r * 512 + c];
    x[r * 256 + c]  = qemb[r * 512 + 256 + c];
}

// mask dtype sniffing: jnp bool may arrive as int32 / uint8 / float32.
__global__ void detect_mask(const unsigned int* __restrict__ w)
{
    if (threadIdx.x == 0) { g_mask_float = 0; g_mask_byte = 0; }
    __syncthreads();
    int fl = 0, by = 0;
    for (int i = threadIdx.x; i < 65536; i += 256) {   // 256 KB, safe for all widths
        unsigned int v = w[i];
        if (v == 0x3F800000u) fl = 1;
        else if (v > 1u) by = 1;
    }
    if (fl) atomicOr(&g_mask_float, 1);
    if (by) atomicOr(&g_mask_byte, 1);
}

__global__ void convert_mask(const void* __restrict__ mask, float* __restrict__ bias, long n)
{
    long i = (long)blockIdx.x * 256 + threadIdx.x;
    if (i >= n) return;
    int blocked;
    if (g_mask_float)     blocked = ((const float*)mask)[i] != 0.f;
    else if (g_mask_byte) blocked = ((const unsigned char*)mask)[i] != 0;
    else                  blocked = ((const int*)mask)[i] != 0;
    bias[i] = blocked ? -1e30f : 0.f;
}

__global__ void copy_out(const float* __restrict__ x, float* __restrict__ out, int n)
{
    int i = blockIdx.x * 256 + threadIdx.x;
    if (i < n) out[i] = x[i];
}

// ------------------------- host driver -------------------------

static inline dim3 grid_tn(int M, int N, int batch) { return dim3((N + 63) / 64, (M + 63) / 64, batch); }
static inline dim3 grid_nn(int M, int N, int batch) { return dim3((N + 31) / 32, (M + 31) / 32, batch); }

extern "C" void kernel_launch(void* const* d_in, const int* in_sizes, int n_in,
                              void* d_out, int out_size)
{
    const float* srcs    = (const float*)d_in[0];
    const float* pos     = (const float*)d_in[1];
    const float* qemb    = (const float*)d_in[2];
    const void*  mask    = d_in[3];
    const float* sa_in_w = (const float*)d_in[4];
    const float* sa_in_b = (const float*)d_in[5];
    const float* sa_ow   = (const float*)d_in[6];
    const float* sa_ob   = (const float*)d_in[7];
    const float* ca_in_w = (const float*)d_in[8];
    const float* ca_in_b = (const float*)d_in[9];
    const float* ca_ow   = (const float*)d_in[10];
    const float* ca_ob   = (const float*)d_in[11];
    const float* ln1w = (const float*)d_in[12];
    const float* ln1b = (const float*)d_in[13];
    const float* ln2w = (const float*)d_in[14];
    const float* ln2b = (const float*)d_in[15];
    const float* ln3w = (const float*)d_in[16];
    const float* ln3b = (const float*)d_in[17];
    const float* ff1w = (const float*)d_in[18];
    const float* ff1b = (const float*)d_in[19];
    const float* ff2w = (const float*)d_in[20];
    const float* ff2b = (const float*)d_in[21];

    float *srct, *srcpos, *mb, *Kb, *Vb, *cas, *sas, *x, *qe, *t1, *t2, *qb, *kb, *vb, *ao, *ffh;
    cudaGetSymbolAddress((void**)&srct, g_srct);
    cudaGetSymbolAddress((void**)&srcpos, g_srcpos);
    cudaGetSymbolAddress((void**)&mb, g_maskbias);
    cudaGetSymbolAddress((void**)&Kb, g_Kbuf);
    cudaGetSymbolAddress((void**)&Vb, g_Vbuf);
    cudaGetSymbolAddress((void**)&cas, g_cascores);
    cudaGetSymbolAddress((void**)&sas, g_sascores);
    cudaGetSymbolAddress((void**)&x, g_x);
    cudaGetSymbolAddress((void**)&qe, g_qe);
    cudaGetSymbolAddress((void**)&t1, g_t1);
    cudaGetSymbolAddress((void**)&t2, g_t2);
    cudaGetSymbolAddress((void**)&qb, g_qb);
    cudaGetSymbolAddress((void**)&kb, g_kb);
    cudaGetSymbolAddress((void**)&vb, g_vb);
    cudaGetSymbolAddress((void**)&ao, g_ao);
    cudaGetSymbolAddress((void**)&ffh, g_ffh);

    const float scale = 0.17677669529663687f;  // 32^-0.5
    const int C = C_MODEL, S = S_TOTAL;

    // preprocessing
    prep_src<<<dim3((S + 31) / 32, C / 32), dim3(32, 8)>>>(srcs, pos, srct, srcpos);
    init_qx<<<NQ, 256>>>(qemb, qe, x);
    detect_mask<<<1, 256>>>((const unsigned int*)mask);
    convert_mask<<<(MASK_N + 255) / 256, 256>>>(mask, mb, (long)MASK_N);

    for (int l = 0; l < NLAYERS; l++) {
        const float* saw = sa_in_w + (long)l * 3 * C * C;
        const float* sab = sa_in_b + (long)l * 3 * C;
        const float* caw = ca_in_w + (long)l * 3 * C * C;
        const float* cab = ca_in_b + (long)l * 3 * C;

        // ---- self attention ----
        add_vec<<<(NQ * C + 255) / 256, 256>>>(x, qe, t1, NQ * C);
        gemm_tn<<<grid_tn(NQ, C, 1), 256>>>(t1, saw,             sab,         nullptr, qb, NQ, C, C, C, C, C, 0, 0, 0, 0, scale, 0);
        gemm_tn<<<grid_tn(NQ, C, 1), 256>>>(t1, saw + C * C,     sab + C,     nullptr, kb, NQ, C, C, C, C, C, 0, 0, 0, 0, 1.f, 0);
        gemm_tn<<<grid_tn(NQ, C, 1), 256>>>(x,  saw + 2 * C * C, sab + 2 * C, nullptr, vb, NQ, C, C, C, C, C, 0, 0, 0, 0, 1.f, 0);
        gemm_tn<<<grid_tn(NQ, NQ, NHEADS), 256>>>(qb, kb, nullptr, nullptr, sas,
            NQ, NQ, DHEAD, C, C, NQ, 0, DHEAD, DHEAD, (long)NQ * NQ, 1.f, 0);
        softmax_rows<<<NHEADS * NQ, 256>>>(sas, NQ);
        gemm_nn<<<grid_nn(NQ, DHEAD, NHEADS), 256>>>(sas, vb, ao,
            NQ, DHEAD, NQ, NQ, C, C, (long)NQ * NQ, DHEAD, DHEAD);
        gemm_tn<<<grid_tn(NQ, C, 1), 256>>>(ao, sa_ow + (long)l * C * C, sa_ob + (long)l * C, nullptr, t2,
            NQ, C, C, C, C, C, 0, 0, 0, 0, 1.f, 0);
        residual_ln<<<NQ, 256>>>(x, t2, ln2w + (long)l * C, ln2b + (long)l * C);

        // ---- cross attention ----
        add_vec<<<(NQ * C + 255) / 256, 256>>>(x, qe, t1, NQ * C);
        gemm_tn<<<grid_tn(NQ, C, 1), 256>>>(t1, caw, cab, nullptr, qb, NQ, C, C, C, C, C, 0, 0, 0, 0, scale, 0);
        gemm_tn<<<grid_tn(S, C, 1), 256>>>(srcpos, caw + C * C,     cab + C,     nullptr, Kb, S, C, C, C, C, C, 0, 0, 0, 0, 1.f, 0);
        gemm_tn<<<grid_tn(S, C, 1), 256>>>(srct,   caw + 2 * C * C, cab + 2 * C, nullptr, Vb, S, C, C, C, C, C, 0, 0, 0, 0, 1.f, 0);
        gemm_tn<<<grid_tn(NQ, S, NHEADS), 256>>>(qb, Kb, nullptr, mb, cas,
            NQ, S, DHEAD, C, C, S, S, DHEAD, DHEAD, (long)NQ * S, 1.f, 0);
        softmax_rows<<<NHEADS * NQ, 256>>>(cas, S);
        gemm_nn<<<grid_nn(NQ, DHEAD, NHEADS), 256>>>(cas, Vb, ao,
            NQ, DHEAD, S, S, C, C, (long)NQ * S, DHEAD, DHEAD);
        gemm_tn<<<grid_tn(NQ, C, 1), 256>>>(ao, ca_ow + (long)l * C * C, ca_ob + (long)l * C, nullptr, t2,
            NQ, C, C, C, C, C, 0, 0, 0, 0, 1.f, 0);
        residual_ln<<<NQ, 256>>>(x, t2, ln1w + (long)l * C, ln1b + (long)l * C);

        // ---- FFN ----
        gemm_tn<<<grid_tn(NQ, DFF, 1), 256>>>(x, ff1w + (long)l * DFF * C, ff1b + (long)l * DFF, nullptr, ffh,
            NQ, DFF, C, C, C, DFF, 0, 0, 0, 0, 1.f, 1);
        gemm_tn<<<grid_tn(NQ, C, 1), 256>>>(ffh, ff2w + (long)l * C * DFF, ff2b + (long)l * C, nullptr, t2,
            NQ, C, DFF, DFF, DFF, C, 0, 0, 0, 0, 1.f, 0);
        residual_ln<<<NQ, 256>>>(x, t2, ln3w + (long)l * C, ln3b + (long)l * C);
    }

    copy_out<<<(NQ * C + 255) / 256, 256>>>(x, (float*)d_out, NQ * C);
}

// round 2
// speedup vs baseline: 3.5666x; 3.5666x over previous
#include <cuda_runtime.h>
#include <math.h>

#define S_TOTAL 15768
#define NQ 300
#define C_MODEL 256
#define NHEADS 8
#define DHEAD 32
#define NLAYERS 6
#define DFF 1024
#define CHUNK 128
#define NCHUNK 124            // ceil(15768/128)
#define SW 493                // mask words per query: ceil(15768/32)

// ------------------------- scratch (device globals) -------------------------
__device__ float g_srct[S_TOTAL * C_MODEL];       // src^T [S, C]
__device__ float g_srcpos[S_TOTAL * C_MODEL];     // (src+pos)^T [S, C]
__device__ unsigned g_mbits[NQ * SW];             // bit=1 -> allowed
__device__ float g_kvall[(size_t)NLAYERS * S_TOTAL * 512];  // [l][S][512]: K|V
__device__ float g_opart[(size_t)NCHUNK * NHEADS * NQ * DHEAD];
__device__ float2 g_mspart[NCHUNK * NHEADS * NQ];
__device__ float g_x[NQ * C_MODEL];
__device__ float g_qe[NQ * C_MODEL];
__device__ float g_t1[NQ * C_MODEL];
__device__ float g_t2[NQ * C_MODEL];
__device__ float g_qkv[NQ * 3 * C_MODEL];
__device__ float g_qb[NQ * C_MODEL];
__device__ float g_sas[NHEADS * NQ * NQ];
__device__ float g_ao[NQ * C_MODEL];
__device__ float g_ffh[NQ * DFF];
__device__ int   g_mask_float;
__device__ int   g_mask_byte;

// ------------------------- unified SGEMM -------------------------
// C[M,N] = act( alpha_col * (A[M,K] @ B[N,K]^T + bias[N]) )
// A chosen per n-tile: n0 < nsplit -> A0 else A1. alpha applied when n < nscale.
// Batched over blockIdx.z with strides.
__global__ __launch_bounds__(256) void sgemm(
    const float* __restrict__ A0, const float* __restrict__ A1, int nsplit,
    const float* __restrict__ B, const float* __restrict__ bias,
    float* __restrict__ Cc, int M, int N, int K,
    int lda, int ldb, int ldc,
    long sA, long sB, long sbias, long sC,
    float alpha, int nscale, int relu)
{
    __shared__ float As[16][64];
    __shared__ float Bs[16][64];
    int z = blockIdx.z;
    int m0 = blockIdx.y * 64, n0 = blockIdx.x * 64;
    const float* A = ((n0 >= nsplit) ? A1 : A0) + (long)z * sA;
    const float* Bp = B + (long)z * sB;
    const float* bp = bias ? bias + (long)z * sbias : nullptr;
    float* Cp = Cc + (long)z * sC;
    int tid = threadIdx.x;
    int lr = tid >> 2, lc = tid & 3;     // load: row 0..63, float4 col 0..3
    int tm = tid >> 4, tn = tid & 15;    // compute 4x4
    float acc[4][4] = {};
    for (int k0 = 0; k0 < K; k0 += 16) {
        float4 a4 = make_float4(0.f, 0.f, 0.f, 0.f);
        float4 b4 = make_float4(0.f, 0.f, 0.f, 0.f);
        if (m0 + lr < M) a4 = *(const float4*)&A[(long)(m0 + lr) * lda + k0 + lc * 4];
        if (n0 + lr < N) b4 = *(const float4*)&Bp[(long)(n0 + lr) * ldb + k0 + lc * 4];
        __syncthreads();
        As[lc * 4 + 0][lr] = a4.x; As[lc * 4 + 1][lr] = a4.y;
        As[lc * 4 + 2][lr] = a4.z; As[lc * 4 + 3][lr] = a4.w;
        Bs[lc * 4 + 0][lr] = b4.x; Bs[lc * 4 + 1][lr] = b4.y;
        Bs[lc * 4 + 2][lr] = b4.z; Bs[lc * 4 + 3][lr] = b4.w;
        __syncthreads();
        #pragma unroll
        for (int k = 0; k < 16; k++) {
            float4 av = *(const float4*)&As[k][tm * 4];
            float4 bv = *(const float4*)&Bs[k][tn * 4];
            acc[0][0] += av.x * bv.x; acc[0][1] += av.x * bv.y;
            acc[0][2] += av.x * bv.z; acc[0][3] += av.x * bv.w;
            acc[1][0] += av.y * bv.x; acc[1][1] += av.y * bv.y;
            acc[1][2] += av.y * bv.z; acc[1][3] += av.y * bv.w;
            acc[2][0] += av.z * bv.x; acc[2][1] += av.z * bv.y;
            acc[2][2] += av.z * bv.z; acc[2][3] += av.z * bv.w;
            acc[3][0] += av.w * bv.x; acc[3][1] += av.w * bv.y;
            acc[3][2] += av.w * bv.z; acc[3][3] += av.w * bv.w;
        }
    }
    #pragma unroll
    for (int i = 0; i < 4; i++) {
        int m = m0 + tm * 4 + i;
        if (m >= M) continue;
        #pragma unroll
        for (int j = 0; j < 4; j++) {
            int n = n0 + tn * 4 + j;
            if (n >= N) continue;
            float v = acc[i][j];
            if (bp) v += bp[n];
            if (n < nscale) v *= alpha;
            if (relu) v = fmaxf(v, 0.f);
            Cp[(long)m * ldc + n] = v;
        }
    }
}

// C[M,N] = A[M,K] @ B[K,N], batched (used for SA attention*V, small)
__global__ __launch_bounds__(256) void gemm_nn(
    const float* __restrict__ A, const float* __restrict__ B,
    float* __restrict__ C,
    int M, int N, int K, int lda, int ldb, int ldc,
    long sA, long sB, long sC)
{
    __shared__ float As[32][33];
    __shared__ float Bs[32][33];
    int b = blockIdx.z;
    A += (long)b * sA; B += (long)b * sB; C += (long)b * sC;
    int m0 = blockIdx.y * 32, n0 = blockIdx.x * 32;
    int tid = threadIdx.x;
    int tx = tid & 31, ty = tid >> 5;
    float acc[4] = {};
    for (int k0 = 0; k0 < K; k0 += 32) {
        #pragma unroll
        for (int i = 0; i < 4; i++) {
            int idx = tid + i * 256;
            int r = idx >> 5, cc = idx & 31;
            float va = 0.f, vb = 0.f;
            if (m0 + r < M && k0 + cc < K) va = A[(long)(m0 + r) * lda + k0 + cc];
            if (k0 + r < K && n0 + cc < N) vb = B[(long)(k0 + r) * ldb + n0 + cc];
            As[r][cc] = va;
            Bs[r][cc] = vb;
        }
        __syncthreads();
        #pragma unroll
        for (int k = 0; k < 32; k++) {
            float bv = Bs[k][tx];
            #pragma unroll
            for (int i = 0; i < 4; i++)
                acc[i] += As[ty + i * 8][k] * bv;
        }
        __syncthreads();
    }
    #pragma unroll
    for (int i = 0; i < 4; i++) {
        int m = m0 + ty + i * 8;
        int n = n0 + tx;
        if (m < M && n < N) C[(long)m * ldc + n] = acc[i];
    }
}

// ------------------------- flash cross-attention -------------------------
// One CTA = (chunk of 128 keys, head). 160 threads, 2 queries/thread.
__global__ __launch_bounds__(160, 1) void flash_ca(
    const float* __restrict__ Qm,     // [300][256] (already scaled)
    const float* __restrict__ KV,     // [S][512]: cols 0-255 K, 256-511 V
    const unsigned* __restrict__ mbits,
    float* __restrict__ Opart, float2* __restrict__ MSpart)
{
    __shared__ float4 Ks[CHUNK][8];
    __shared__ float4 Vs[CHUNK][8];
    int ch = blockIdx.x, h = blockIdx.y;
    int s0 = ch * CHUNK;
    int nk = min(CHUNK, S_TOTAL - s0);
    int tid = threadIdx.x;
    for (int idx = tid; idx < nk * 8; idx += 160) {
        int j = idx >> 3, f = idx & 7;
        const float4* row = (const float4*)&KV[(long)(s0 + j) * 512];
        Ks[j][f] = row[h * 8 + f];
        Vs[j][f] = row[64 + h * 8 + f];
    }
    __syncthreads();

    int q0 = tid * 2;
    bool a0 = (q0 < NQ), a1 = (q0 + 1 < NQ);
    float Qa[32], Qb[32], Oa[32] = {}, Ob[32] = {};
    #pragma unroll
    for (int f = 0; f < 8; f++) {
        ((float4*)Qa)[f] = a0 ? *(const float4*)&Qm[(long)q0 * 256 + h * 32 + f * 4]
                              : make_float4(0.f, 0.f, 0.f, 0.f);
        ((float4*)Qb)[f] = a1 ? *(const float4*)&Qm[(long)(q0 + 1) * 256 + h * 32 + f * 4]
                              : make_float4(0.f, 0.f, 0.f, 0.f);
    }
    float ma = -3.4e38f, mb = -3.4e38f, sa = 0.f, sb = 0.f;

    for (int jw = 0; jw < nk; jw += 32) {
        int wi = (s0 + jw) >> 5;
        unsigned w0 = a0 ? mbits[q0 * SW + wi] : 0u;
        unsigned w1 = a1 ? mbits[(q0 + 1) * SW + wi] : 0u;
        unsigned wu = w0 | w1;
        int jend = min(32, nk - jw);
        for (int jj = 0; jj < jend; jj++) {
            unsigned bit = 1u << jj;
            if (!(wu & bit)) continue;
            int j = jw + jj;
            float d0 = 0.f, d1 = 0.f;
            #pragma unroll
            for (int f = 0; f < 8; f++) {
                float4 kk = Ks[j][f];
                d0 += Qa[4*f+0]*kk.x + Qa[4*f+1]*kk.y + Qa[4*f+2]*kk.z + Qa[4*f+3]*kk.w;
                d1 += Qb[4*f+0]*kk.x + Qb[4*f+1]*kk.y + Qb[4*f+2]*kk.z + Qb[4*f+3]*kk.w;
            }
            if (w0 & bit) {
                float p;
                if (d0 > ma) {
                    float c = __expf(ma - d0);
                    sa = sa * c + 1.f;
                    #pragma unroll
                    for (int d = 0; d < 32; d++) Oa[d] *= c;
                    ma = d0; p = 1.f;
                } else { p = __expf(d0 - ma); sa += p; }
                #pragma unroll
                for (int f = 0; f < 8; f++) {
                    float4 vv = Vs[j][f];
                    Oa[4*f+0] += p * vv.x; Oa[4*f+1] += p * vv.y;
                    Oa[4*f+2] += p * vv.z; Oa[4*f+3] += p * vv.w;
                }
            }
            if (w1 & bit) {
                float p;
                if (d1 > mb) {
                    float c = __expf(mb - d1);
                    sb = sb * c + 1.f;
                    #pragma unroll
                    for (int d = 0; d < 32; d++) Ob[d] *= c;
                    mb = d1; p = 1.f;
                } else { p = __expf(d1 - mb); sb += p; }
                #pragma unroll
                for (int f = 0; f < 8; f++) {
                    float4 vv = Vs[j][f];
                    Ob[4*f+0] += p * vv.x; Ob[4*f+1] += p * vv.y;
                    Ob[4*f+2] += p * vv.z; Ob[4*f+3] += p * vv.w;
                }
            }
        }
    }
    long base = (long)(ch * NHEADS + h) * NQ;
    if (a0) {
        float4* op = (float4*)&Opart[(base + q0) * DHEAD];
        #pragma unroll
        for (int f = 0; f < 8; f++) op[f] = ((float4*)Oa)[f];
        MSpart[base + q0] = make_float2(ma, sa);
    }
    if (a1) {
        float4* op = (float4*)&Opart[(base + q0 + 1) * DHEAD];
        #pragma unroll
        for (int f = 0; f < 8; f++) op[f] = ((float4*)Ob)[f];
        MSpart[base + q0 + 1] = make_float2(mb, sb);
    }
}

__global__ void ca_combine(const float* __restrict__ Opart,
                           const float2* __restrict__ MSpart,
                           float* __restrict__ ao)
{
    int idx = blockIdx.x * blockDim.x + threadIdx.x;
    if (idx >= NHEADS * NQ) return;
    int h = idx / NQ, q = idx % NQ;
    float m = -3.4e38f, s = 0.f;
    float O[32] = {};
    for (int ch = 0; ch < NCHUNK; ch++) {
        long base = (long)(ch * NHEADS + h) * NQ + q;
        float2 ms = MSpart[base];
        if (ms.y <= 0.f) continue;
        if (ms.x > m) {
            float c = (m > -3.0e38f) ? __expf(m - ms.x) : 0.f;
            s *= c;
            #pragma unroll
            for (int d = 0; d < 32; d++) O[d] *= c;
            m = ms.x;
        }
        float c2 = __expf(ms.x - m);
        const float4* op = (const float4*)&Opart[base * DHEAD];
        s += ms.y * c2;
        #pragma unroll
        for (int f = 0; f < 8; f++) {
            float4 v = op[f];
            O[4*f+0] += c2 * v.x; O[4*f+1] += c2 * v.y;
            O[4*f+2] += c2 * v.z; O[4*f+3] += c2 * v.w;
        }
    }
    float inv = 1.f / s;
    #pragma unroll
    for (int d = 0; d < 32; d++) ao[(long)q * 256 + h * 32 + d] = O[d] * inv;
}

// ------------------------- small kernels -------------------------
__global__ __launch_bounds__(256) void softmax_rows(float* __restrict__ P, int rowlen)
{
    long r = blockIdx.x;
    float* p = P + r * (long)rowlen;
    int tid = threadIdx.x;
    float m = -3.4e38f, s = 0.f;
    for (int i = tid; i < rowlen; i += 256) {
        float x = p[i];
        if (x > m) { s = s * __expf(m - x) + 1.f; m = x; }
        else       { s += __expf(x - m); }
    }
    __shared__ float sm[256], ss[256];
    sm[tid] = m; ss[tid] = s;
    __syncthreads();
    for (int off = 128; off > 0; off >>= 1) {
        if (tid < off) {
            float m1 = sm[tid], m2 = sm[tid + off];
            float s1 = ss[tid], s2 = ss[tid + off];
            float mm = fmaxf(m1, m2);
            sm[tid] = mm;
            ss[tid] = s1 * __expf(m1 - mm) + s2 * __expf(m2 - mm);
        }
        __syncthreads();
    }
    float Mx = sm[0];
    float inv = 1.f / ss[0];
    for (int i = tid; i < rowlen; i += 256)
        p[i] = __expf(p[i] - Mx) * inv;
}

__global__ __launch_bounds__(256) void residual_ln(
    float* __restrict__ x, const float* __restrict__ res,
    const float* __restrict__ w, const float* __restrict__ b)
{
    int r = blockIdx.x;
    int c = threadIdx.x;
    float v = x[r * 256 + c] + res[r * 256 + c];
    __shared__ float red[256];
    red[c] = v; __syncthreads();
    for (int off = 128; off > 0; off >>= 1) { if (c < off) red[c] += red[c + off]; __syncthreads(); }
    float mean = red[0] * (1.f / 256.f);
    __syncthreads();
    float d = v - mean;
    red[c] = d * d; __syncthreads();
    for (int off = 128; off > 0; off >>= 1) { if (c < off) red[c] += red[c + off]; __syncthreads(); }
    float var = red[0] * (1.f / 256.f);
    x[r * 256 + c] = d * rsqrtf(var + 1e-5f) * w[c] + b[c];
}

__global__ void add_vec(const float* a, const float* b, float* c, int n)
{
    int i = blockIdx.x * 256 + threadIdx.x;
    if (i < n) c[i] = a[i] + b[i];
}

__global__ void prep_src(const float* __restrict__ srcs, const float* __restrict__ pos,
                         float* __restrict__ srct, float* __restrict__ srcpos)
{
    __shared__ float t1[32][33], t2[32][33];
    int s0 = blockIdx.x * 32, c0 = blockIdx.y * 32;
    int tx = threadIdx.x, ty = threadIdx.y;  // (32,8)
    #pragma unroll
    for (int i = 0; i < 4; i++) {
        int c = c0 + ty + i * 8, s = s0 + tx;
        float a = 0.f, f = 0.f;
        if (s < S_TOTAL) { a = srcs[(long)c * S_TOTAL + s]; f = pos[(long)c * S_TOTAL + s]; }
        t1[ty + i * 8][tx] = a;
        t2[ty + i * 8][tx] = f;
    }
    __syncthreads();
    #pragma unroll
    for (int i = 0; i < 4; i++) {
        int s = s0 + ty + i * 8, c = c0 + tx;
        if (s < S_TOTAL) {
            float a = t1[tx][ty + i * 8];
            float f = t2[tx][ty + i * 8];
            srct[(long)s * 256 + c]   = a;
            srcpos[(long)s * 256 + c] = a + f;
        }
    }
}

__global__ void init_qx(const float* __restrict__ qemb, float* __restrict__ qe, float* __restrict__ x)
{
    int r = blockIdx.x, c = threadIdx.x;
    qe[r * 256 + c] = qemb[r * 512 + c];
    x[r * 256 + c]  = qemb[r * 512 + 256 + c];
}

__global__ void detect_mask(const unsigned int* __restrict__ w)
{
    if (threadIdx.x == 0) { g_mask_float = 0; g_mask_byte = 0; }
    __syncthreads();
    int fl = 0, by = 0;
    for (int i = threadIdx.x; i < 65536; i += 256) {
        unsigned int v = w[i];
        if (v == 0x3F800000u) fl = 1;
        else if (v > 1u) by = 1;
    }
    if (fl) atomicOr(&g_mask_float, 1);
    if (by) atomicOr(&g_mask_byte, 1);
}

__global__ void mask_to_bits(const void* __restrict__ mask, unsigned* __restrict__ bits)
{
    int idx = blockIdx.x * 256 + threadIdx.x;
    if (idx >= NQ * SW) return;
    int q = idx / SW, w = idx % SW;
    unsigned out = 0;
    int base = w * 32;
    int fl = g_mask_float, by = g_mask_byte;
    #pragma unroll 4
    for (int j = 0; j < 32; j++) {
        int s = base + j;
        if (s >= S_TOTAL) break;
        long off = (long)q * S_TOTAL + s;
        int blocked;
        if (fl)      blocked = ((const float*)mask)[off] != 0.f;
        else if (by) blocked = ((const unsigned char*)mask)[off] != 0;
        else         blocked = ((const int*)mask)[off] != 0;
        if (!blocked) out |= 1u << j;
    }
    bits[idx] = out;
}

__global__ void copy_out(const float* __restrict__ x, float* __restrict__ out, int n)
{
    int i = blockIdx.x * 256 + threadIdx.x;
    if (i < n) out[i] = x[i];
}

// ------------------------- host driver -------------------------
static inline dim3 g64(int M, int N, int z) { return dim3((N + 63) / 64, (M + 63) / 64, z); }

extern "C" void kernel_launch(void* const* d_in, const int* in_sizes, int n_in,
                              void* d_out, int out_size)
{
    const float* srcs    = (const float*)d_in[0];
    const float* pos     = (const float*)d_in[1];
    const float* qemb    = (const float*)d_in[2];
    const void*  mask    = d_in[3];
    const float* sa_in_w = (const float*)d_in[4];
    const float* sa_in_b = (const float*)d_in[5];
    const float* sa_ow   = (const float*)d_in[6];
    const float* sa_ob   = (const float*)d_in[7];
    const float* ca_in_w = (const float*)d_in[8];
    const float* ca_in_b = (const float*)d_in[9];
    const float* ca_ow   = (const float*)d_in[10];
    const float* ca_ob   = (const float*)d_in[11];
    const float* ln1w = (const float*)d_in[12];
    const float* ln1b = (const float*)d_in[13];
    const float* ln2w = (const float*)d_in[14];
    const float* ln2b = (const float*)d_in[15];
    const float* ln3w = (const float*)d_in[16];
    const float* ln3b = (const float*)d_in[17];
    const float* ff1w = (const float*)d_in[18];
    const float* ff1b = (const float*)d_in[19];
    const float* ff2w = (const float*)d_in[20];
    const float* ff2b = (const float*)d_in[21];

    float *srct, *srcpos, *kvall, *opart, *x, *qe, *t1, *t2, *qkv, *qb, *sas, *ao, *ffh;
    float2* mspart; unsigned* mbits;
    cudaGetSymbolAddress((void**)&srct, g_srct);
    cudaGetSymbolAddress((void**)&srcpos, g_srcpos);
    cudaGetSymbolAddress((void**)&mbits, g_mbits);
    cudaGetSymbolAddress((void**)&kvall, g_kvall);
    cudaGetSymbolAddress((void**)&opart, g_opart);
    cudaGetSymbolAddress((void**)&mspart, g_mspart);
    cudaGetSymbolAddress((void**)&x, g_x);
    cudaGetSymbolAddress((void**)&qe, g_qe);
    cudaGetSymbolAddress((void**)&t1, g_t1);
    cudaGetSymbolAddress((void**)&t2, g_t2);
    cudaGetSymbolAddress((void**)&qkv, g_qkv);
    cudaGetSymbolAddress((void**)&qb, g_qb);
    cudaGetSymbolAddress((void**)&sas, g_sas);
    cudaGetSymbolAddress((void**)&ao, g_ao);
    cudaGetSymbolAddress((void**)&ffh, g_ffh);

    const float scale = 0.17677669529663687f;  // 32^-0.5
    const int C = C_MODEL, S = S_TOTAL;
    const int BIG = 1 << 30;

    // preprocessing
    prep_src<<<dim3((S + 31) / 32, C / 32), dim3(32, 8)>>>(srcs, pos, srct, srcpos);
    init_qx<<<NQ, 256>>>(qemb, qe, x);
    detect_mask<<<1, 256>>>((const unsigned int*)mask);
    mask_to_bits<<<(NQ * SW + 255) / 256, 256>>>(mask, mbits);

    // all-layer K/V projection: [l][S][512], cols 0-255 from srcpos (K), 256-511 from srct (V)
    sgemm<<<g64(S, 512, NLAYERS), 256>>>(
        srcpos, srct, 256,
        ca_in_w + C * C, ca_in_b + C,
        kvall, S, 512, C, C, C, 512,
        0L, (long)3 * C * C, (long)3 * C, (long)S * 512,
        1.f, 0, 0);

    for (int l = 0; l < NLAYERS; l++) {
        const float* saw = sa_in_w + (long)l * 3 * C * C;
        const float* sab = sa_in_b + (long)l * 3 * C;
        const float* caw = ca_in_w + (long)l * 3 * C * C;
        const float* cab = ca_in_b + (long)l * 3 * C;
        const float* kvl = kvall + (long)l * S * 512;

        // ---- self attention ----
        add_vec<<<(NQ * C + 255) / 256, 256>>>(x, qe, t1, NQ * C);
        // fused QKV projection: cols 0-511 use t1 (q,k), 512-767 use x (v); scale q cols
        sgemm<<<g64(NQ, 3 * C, 1), 256>>>(t1, x, 512, saw, sab, qkv,
            NQ, 3 * C, C, C, C, 3 * C, 0, 0, 0, 0, scale, C, 0);
        // scores: per-head q @ k^T
        sgemm<<<g64(NQ, NQ, NHEADS), 256>>>(qkv, nullptr, BIG, qkv + C, nullptr, sas,
            NQ, NQ, DHEAD, 3 * C, 3 * C, NQ, 32L, 32L, 0, (long)NQ * NQ, 1.f, 0, 0);
        softmax_rows<<<NHEADS * NQ, 256>>>(sas, NQ);
        gemm_nn<<<dim3(1, (NQ + 31) / 32, NHEADS), 256>>>(sas, qkv + 2 * C, ao,
            NQ, DHEAD, NQ, NQ, 3 * C, C, (long)NQ * NQ, 32L, 32L);
        sgemm<<<g64(NQ, C, 1), 256>>>(ao, nullptr, BIG, sa_ow + (long)l * C * C,
            sa_ob + (long)l * C, t2, NQ, C, C, C, C, C, 0, 0, 0, 0, 1.f, 0, 0);
        residual_ln<<<NQ, 256>>>(x, t2, ln2w + (long)l * C, ln2b + (long)l * C);

        // ---- cross attention (flash) ----
        add_vec<<<(NQ * C + 255) / 256, 256>>>(x, qe, t1, NQ * C);
        sgemm<<<g64(NQ, C, 1), 256>>>(t1, nullptr, BIG, caw, cab, qb,
            NQ, C, C, C, C, C, 0, 0, 0, 0, scale, C, 0);
        flash_ca<<<dim3(NCHUNK, NHEADS), 160>>>(qb, kvl, mbits, opart, mspart);
        ca_combine<<<(NHEADS * NQ + 255) / 256, 256>>>(opart, mspart, ao);
        sgemm<<<g64(NQ, C, 1), 256>>>(ao, nullptr, BIG, ca_ow + (long)l * C * C,
            ca_ob + (long)l * C, t2, NQ, C, C, C, C, C, 0, 0, 0, 0, 1.f, 0, 0);
        residual_ln<<<NQ, 256>>>(x, t2, ln1w + (long)l * C, ln1b + (long)l * C);

        // ---- FFN ----
        sgemm<<<g64(NQ, DFF, 1), 256>>>(x, nullptr, BIG, ff1w + (long)l * DFF * C,
            ff1b + (long)l * DFF, ffh, NQ, DFF, C, C, C, DFF, 0, 0, 0, 0, 1.f, 0, 1);
        sgemm<<<g64(NQ, C, 1), 256>>>(ffh, nullptr, BIG, ff2w + (long)l * C * DFF,
            ff2b + (long)l * C, t2, NQ, C, DFF, DFF, DFF, C, 0, 0, 0, 0, 1.f, 0, 0);
        residual_ln<<<NQ, 256>>>(x, t2, ln3w + (long)l * C, ln3b + (long)l * C);
    }

    copy_out<<<(NQ * C + 255) / 256, 256>>>(x, (float*)d_out, NQ * C);
}

// round 4
// speedup vs baseline: 3.9290x; 1.1016x over previous
#include <cuda_runtime.h>
#include <math.h>

#define S_TOTAL 15768
#define NQ 300
#define C_MODEL 256
#define NHEADS 8
#define DHEAD 32
#define NLAYERS 6
#define DFF 1024
#define CHUNK 128
#define NCHUNK 124            // ceil(15768/128)
#define SW 493                // mask words per query: ceil(15768/32)

// ------------------------- scratch (device globals) -------------------------
__device__ float g_srct[S_TOTAL * C_MODEL];       // src^T [S, C]
__device__ float g_srcpos[S_TOTAL * C_MODEL];     // (src+pos)^T [S, C]
__device__ unsigned g_mbits[NQ * SW];             // bit=1 -> allowed
__device__ float g_kvall[(size_t)NLAYERS * S_TOTAL * 512];  // [l][S][512]: K|V
__device__ float g_opart[(size_t)NCHUNK * NHEADS * NQ * DHEAD];
__device__ float2 g_mspart[NCHUNK * NHEADS * NQ];
__device__ float g_x[NQ * C_MODEL];
__device__ float g_qe[NQ * C_MODEL];
__device__ float g_t2[NQ * C_MODEL];
__device__ float g_qkv[NQ * 3 * C_MODEL];
__device__ float g_qb[NQ * C_MODEL];
__device__ float g_sas[NHEADS * NQ * NQ];
__device__ float g_ao[NQ * C_MODEL];
__device__ float g_ffh[NQ * DFF];
__device__ int   g_mask_float;
__device__ int   g_mask_byte;

// ------------------------- 3xTF32 tensor-core GEMM -------------------------
// C[M,N] = act( alpha_col * (A[M,K] @ B[N,K]^T + bias[N]) )
// A per n-tile: n0 < nsplit -> (A0 [+ Aadd]) else A1.  alpha when n < nscale.
// Batched over blockIdx.z with long strides. K must be a multiple of 32,
// lda/ldb multiples of 4 (float4 loads). Precision: 3-pass TF32 (fp32-class).

__device__ __forceinline__ void split_tf32(float v, unsigned& hi, unsigned& lo)
{
    unsigned h;
    asm("cvt.rna.tf32.f32 %0, %1;" : "=r"(h) : "f"(v));
    hi = h;
    float l = v - __uint_as_float(h);
    asm("cvt.rna.tf32.f32 %0, %1;" : "=r"(lo) : "f"(l));
}

__device__ __forceinline__ void mma8(float c[4], const unsigned a[4], const unsigned b[2])
{
    asm volatile(
        "mma.sync.aligned.m16n8k8.row.col.f32.tf32.tf32.f32 "
        "{%0,%1,%2,%3}, {%4,%5,%6,%7}, {%8,%9}, {%0,%1,%2,%3};"
        : "+f"(c[0]), "+f"(c[1]), "+f"(c[2]), "+f"(c[3])
        : "r"(a[0]), "r"(a[1]), "r"(a[2]), "r"(a[3]), "r"(b[0]), "r"(b[1]));
}

template <int BM>
__global__ __launch_bounds__(256) void tfgemm(
    const float* __restrict__ A0, const float* __restrict__ A1,
    const float* __restrict__ Aadd, int nsplit,
    const float* __restrict__ B, const float* __restrict__ bias,
    float* __restrict__ Cc, int M, int N, int K,
    int lda, int ldb, int ldc,
    long sA, long sB, long sbias, long sC,
    float alpha, int nscale, int relu)
{
    constexpr int BN = 64, BK = 32;
    constexpr int WMR = BM / 4;       // warp m rows (32 or 16)
    constexpr int MT = WMR / 16;      // m16 tiles per warp (2 or 1)
    constexpr int NT = 4;             // n8 tiles per warp (32/8)
    __shared__ float As[BM][BK + 4];
    __shared__ float Bs[BN][BK + 4];

    int z = blockIdx.z;
    int m0 = blockIdx.y * BM, n0 = blockIdx.x * BN;
    const float* A = ((n0 >= nsplit) ? A1 : A0) + (long)z * sA;
    const float* Aa = (n0 < nsplit) ? Aadd : nullptr;
    const float* Bp = B + (long)z * sB;
    const float* bp = bias ? bias + (long)z * sbias : nullptr;
    float* Cp = Cc + (long)z * sC;

    int tid = threadIdx.x;
    int warp = tid >> 5, lane = tid & 31;
    int gid = lane >> 2, ctg = lane & 3;
    int wm = warp & 3, wn = warp >> 2;     // 4 x 2 warp grid
    int mw = wm * WMR, nw = wn * 32;

    int lr = tid >> 3, lc4 = tid & 7;      // loader: row slice 0..31, float4 col

    float acc[MT][NT][4] = {};

    for (int k0 = 0; k0 < K; k0 += BK) {
        __syncthreads();
        #pragma unroll
        for (int rb = 0; rb < BM; rb += 32) {
            int row = rb + lr;
            float4 v = make_float4(0.f, 0.f, 0.f, 0.f);
            if (m0 + row < M) {
                v = *(const float4*)&A[(long)(m0 + row) * lda + k0 + lc4 * 4];
                if (Aa) {
                    float4 w = *(const float4*)&Aa[(long)(m0 + row) * lda + k0 + lc4 * 4];
                    v.x += w.x; v.y += w.y; v.z += w.z; v.w += w.w;
                }
            }
            *(float4*)&As[row][lc4 * 4] = v;
        }
        #pragma unroll
        for (int rb = 0; rb < BN; rb += 32) {
            int row = rb + lr;
            float4 v = make_float4(0.f, 0.f, 0.f, 0.f);
            if (n0 + row < N)
                v = *(const float4*)&Bp[(long)(n0 + row) * ldb + k0 + lc4 * 4];
            *(float4*)&Bs[row][lc4 * 4] = v;
        }
        __syncthreads();

        #pragma unroll
        for (int ks = 0; ks < BK / 8; ks++) {
            int kk = ks * 8;
            unsigned bh[NT][2], bl[NT][2];
            #pragma unroll
            for (int nt = 0; nt < NT; nt++) {
                float v0 = Bs[nw + nt * 8 + gid][kk + ctg];
                float v1 = Bs[nw + nt * 8 + gid][kk + ctg + 4];
                split_tf32(v0, bh[nt][0], bl[nt][0]);
                split_tf32(v1, bh[nt][1], bl[nt][1]);
            }
            #pragma unroll
            for (int mt = 0; mt < MT; mt++) {
                float a0 = As[mw + mt * 16 + gid][kk + ctg];
                float a1 = As[mw + mt * 16 + gid + 8][kk + ctg];
                float a2 = As[mw + mt * 16 + gid][kk + ctg + 4];
                float a3 = As[mw + mt * 16 + gid + 8][kk + ctg + 4];
                unsigned ah[4], al[4];
                split_tf32(a0, ah[0], al[0]);
                split_tf32(a1, ah[1], al[1]);
                split_tf32(a2, ah[2], al[2]);
                split_tf32(a3, ah[3], al[3]);
                #pragma unroll
                for (int nt = 0; nt < NT; nt++) {
                    mma8(acc[mt][nt], ah, bh[nt]);
                    mma8(acc[mt][nt], al, bh[nt]);
                    mma8(acc[mt][nt], ah, bl[nt]);
                }
            }
        }
    }

    #pragma unroll
    for (int mt = 0; mt < MT; mt++) {
        #pragma unroll
        for (int nt = 0; nt < NT; nt++) {
            #pragma unroll
            for (int e = 0; e < 4; e++) {
                int m = m0 + mw + mt * 16 + gid + (e >> 1) * 8;
                int n = n0 + nw + nt * 8 + 2 * ctg + (e & 1);
                if (m >= M || n >= N) continue;
                float v = acc[mt][nt][e];
                if (bp) v += bp[n];
                if (n < nscale) v *= alpha;
                if (relu) v = fmaxf(v, 0.f);
                Cp[(long)m * ldc + n] = v;
            }
        }
    }
}

// C[M,N] = A[M,K] @ B[K,N], batched (SA attention*V, small)
__global__ __launch_bounds__(256) void gemm_nn(
    const float* __restrict__ A, const float* __restrict__ B,
    float* __restrict__ C,
    int M, int N, int K, int lda, int ldb, int ldc,
    long sA, long sB, long sC)
{
    __shared__ float As[32][33];
    __shared__ float Bs[32][33];
    int b = blockIdx.z;
    A += (long)b * sA; B += (long)b * sB; C += (long)b * sC;
    int m0 = blockIdx.y * 32, n0 = blockIdx.x * 32;
    int tid = threadIdx.x;
    int tx = tid & 31, ty = tid >> 5;
    float acc[4] = {};
    for (int k0 = 0; k0 < K; k0 += 32) {
        #pragma unroll
        for (int i = 0; i < 4; i++) {
            int idx = tid + i * 256;
            int r = idx >> 5, cc = idx & 31;
            float va = 0.f, vb = 0.f;
            if (m0 + r < M && k0 + cc < K) va = A[(long)(m0 + r) * lda + k0 + cc];
            if (k0 + r < K && n0 + cc < N) vb = B[(long)(k0 + r) * ldb + n0 + cc];
            As[r][cc] = va;
            Bs[r][cc] = vb;
        }
        __syncthreads();
        #pragma unroll
        for (int k = 0; k < 32; k++) {
            float bv = Bs[k][tx];
            #pragma unroll
            for (int i = 0; i < 4; i++)
                acc[i] += As[ty + i * 8][k] * bv;
        }
        __syncthreads();
    }
    #pragma unroll
    for (int i = 0; i < 4; i++) {
        int m = m0 + ty + i * 8;
        int n = n0 + tx;
        if (m < M && n < N) C[(long)m * ldc + n] = acc[i];
    }
}

// ------------------------- flash cross-attention -------------------------
__global__ __launch_bounds__(160, 1) void flash_ca(
    const float* __restrict__ Qm,
    const float* __restrict__ KV,
    const unsigned* __restrict__ mbits,
    float* __restrict__ Opart, float2* __restrict__ MSpart)
{
    __shared__ float4 Ks[CHUNK][8];
    __shared__ float4 Vs[CHUNK][8];
    int ch = blockIdx.x, h = blockIdx.y;
    int s0 = ch * CHUNK;
    int nk = min(CHUNK, S_TOTAL - s0);
    int tid = threadIdx.x;
    for (int idx = tid; idx < nk * 8; idx += 160) {
        int j = idx >> 3, f = idx & 7;
        const float4* row = (const float4*)&KV[(long)(s0 + j) * 512];
        Ks[j][f] = row[h * 8 + f];
        Vs[j][f] = row[64 + h * 8 + f];
    }
    __syncthreads();

    int q0 = tid * 2;
    bool a0 = (q0 < NQ), a1 = (q0 + 1 < NQ);
    float Qa[32], Qb[32], Oa[32] = {}, Ob[32] = {};
    #pragma unroll
    for (int f = 0; f < 8; f++) {
        ((float4*)Qa)[f] = a0 ? *(const float4*)&Qm[(long)q0 * 256 + h * 32 + f * 4]
                              : make_float4(0.f, 0.f, 0.f, 0.f);
        ((float4*)Qb)[f] = a1 ? *(const float4*)&Qm[(long)(q0 + 1) * 256 + h * 32 + f * 4]
                              : make_float4(0.f, 0.f, 0.f, 0.f);
    }
    float ma = -3.4e38f, mb = -3.4e38f, sa = 0.f, sb = 0.f;

    for (int jw = 0; jw < nk; jw += 32) {
        int wi = (s0 + jw) >> 5;
        unsigned w0 = a0 ? mbits[q0 * SW + wi] : 0u;
        unsigned w1 = a1 ? mbits[(q0 + 1) * SW + wi] : 0u;
        unsigned wu = w0 | w1;
        int jend = min(32, nk - jw);
        for (int jj = 0; jj < jend; jj++) {
            unsigned bit = 1u << jj;
            if (!(wu & bit)) continue;
            int j = jw + jj;
            float d0 = 0.f, d1 = 0.f;
            #pragma unroll
            for (int f = 0; f < 8; f++) {
                float4 kk = Ks[j][f];
                d0 += Qa[4*f+0]*kk.x + Qa[4*f+1]*kk.y + Qa[4*f+2]*kk.z + Qa[4*f+3]*kk.w;
                d1 += Qb[4*f+0]*kk.x + Qb[4*f+1]*kk.y + Qb[4*f+2]*kk.z + Qb[4*f+3]*kk.w;
            }
            if (w0 & bit) {
                float p;
                if (d0 > ma) {
                    float c = __expf(ma - d0);
                    sa = sa * c + 1.f;
                    #pragma unroll
                    for (int d = 0; d < 32; d++) Oa[d] *= c;
                    ma = d0; p = 1.f;
                } else { p = __expf(d0 - ma); sa += p; }
                #pragma unroll
                for (int f = 0; f < 8; f++) {
                    float4 vv = Vs[j][f];
                    Oa[4*f+0] += p * vv.x; Oa[4*f+1] += p * vv.y;
                    Oa[4*f+2] += p * vv.z; Oa[4*f+3] += p * vv.w;
                }
            }
            if (w1 & bit) {
                float p;
                if (d1 > mb) {
                    float c = __expf(mb - d1);
                    sb = sb * c + 1.f;
                    #pragma unroll
                    for (int d = 0; d < 32; d++) Ob[d] *= c;
                    mb = d1; p = 1.f;
                } else { p = __expf(d1 - mb); sb += p; }
                #pragma unroll
                for (int f = 0; f < 8; f++) {
                    float4 vv = Vs[j][f];
                    Ob[4*f+0] += p * vv.x; Ob[4*f+1] += p * vv.y;
                    Ob[4*f+2] += p * vv.z; Ob[4*f+3] += p * vv.w;
                }
            }
        }
    }
    long base = (long)(ch * NHEADS + h) * NQ;
    if (a0) {
        float4* op = (float4*)&Opart[(base + q0) * DHEAD];
        #pragma unroll
        for (int f = 0; f < 8; f++) op[f] = ((float4*)Oa)[f];
        MSpart[base + q0] = make_float2(ma, sa);
    }
    if (a1) {
        float4* op = (float4*)&Opart[(base + q0 + 1) * DHEAD];
        #pragma unroll
        for (int f = 0; f < 8; f++) op[f] = ((float4*)Ob)[f];
        MSpart[base + q0 + 1] = make_float2(mb, sb);
    }
}

__global__ void ca_combine(const float* __restrict__ Opart,
                           const float2* __restrict__ MSpart,
                           float* __restrict__ ao)
{
    int idx = blockIdx.x * blockDim.x + threadIdx.x;
    if (idx >= NHEADS * NQ) return;
    int h = idx / NQ, q = idx % NQ;
    float m = -3.4e38f, s = 0.f;
    float O[32] = {};
    for (int ch = 0; ch < NCHUNK; ch++) {
        long base = (long)(ch * NHEADS + h) * NQ + q;
        float2 ms = MSpart[base];
        if (ms.y <= 0.f) continue;
        if (ms.x > m) {
            float c = (m > -3.0e38f) ? __expf(m - ms.x) : 0.f;
            s *= c;
            #pragma unroll
            for (int d = 0; d < 32; d++) O[d] *= c;
            m = ms.x;
        }
        float c2 = __expf(ms.x - m);
        const float4* op = (const float4*)&Opart[base * DHEAD];
        s += ms.y * c2;
        #pragma unroll
        for (int f = 0; f < 8; f++) {
            float4 v = op[f];
            O[4*f+0] += c2 * v.x; O[4*f+1] += c2 * v.y;
            O[4*f+2] += c2 * v.z; O[4*f+3] += c2 * v.w;
        }
    }
    float inv = 1.f / s;
    #pragma unroll
    for (int d = 0; d < 32; d++) ao[(long)q * 256 + h * 32 + d] = O[d] * inv;
}

// ------------------------- small kernels -------------------------
__global__ __launch_bounds__(256) void softmax_rows(float* __restrict__ P, int rowlen)
{
    long r = blockIdx.x;
    float* p = P + r * (long)rowlen;
    int tid = threadIdx.x;
    float m = -3.4e38f, s = 0.f;
    for (int i = tid; i < rowlen; i += 256) {
        float x = p[i];
        if (x > m) { s = s * __expf(m - x) + 1.f; m = x; }
        else       { s += __expf(x - m); }
    }
    __shared__ float sm[256], ss[256];
    sm[tid] = m; ss[tid] = s;
    __syncthreads();
    for (int off = 128; off > 0; off >>= 1) {
        if (tid < off) {
            float m1 = sm[tid], m2 = sm[tid + off];
            float s1 = ss[tid], s2 = ss[tid + off];
            float mm = fmaxf(m1, m2);
            sm[tid] = mm;
            ss[tid] = s1 * __expf(m1 - mm) + s2 * __expf(m2 - mm);
        }
        __syncthreads();
    }
    float Mx = sm[0];
    float inv = 1.f / ss[0];
    for (int i = tid; i < rowlen; i += 256)
        p[i] = __expf(p[i] - Mx) * inv;
}

__global__ __launch_bounds__(256) void residual_ln(
    float* __restrict__ x, const float* __restrict__ res,
    const float* __restrict__ w, const float* __restrict__ b)
{
    int r = blockIdx.x;
    int c = threadIdx.x;
    float v = x[r * 256 + c] + res[r * 256 + c];
    __shared__ float red[256];
    red[c] = v; __syncthreads();
    for (int off = 128; off > 0; off >>= 1) { if (c < off) red[c] += red[c + off]; __syncthreads(); }
    float mean = red[0] * (1.f / 256.f);
    __syncthreads();
    float d = v - mean;
    red[c] = d * d; __syncthreads();
    for (int off = 128; off > 0; off >>= 1) { if (c < off) red[c] += red[c + off]; __syncthreads(); }
    float var = red[0] * (1.f / 256.f);
    x[r * 256 + c] = d * rsqrtf(var + 1e-5f) * w[c] + b[c];
}

__global__ void prep_src(const float* __restrict__ srcs, const float* __restrict__ pos,
                         float* __restrict__ srct, float* __restrict__ srcpos)
{
    __shared__ float t1[32][33], t2[32][33];
    int s0 = blockIdx.x * 32, c0 = blockIdx.y * 32;
    int tx = threadIdx.x, ty = threadIdx.y;  // (32,8)
    #pragma unroll
    for (int i = 0; i < 4; i++) {
        int c = c0 + ty + i * 8, s = s0 + tx;
        float a = 0.f, f = 0.f;
        if (s < S_TOTAL) { a = srcs[(long)c * S_TOTAL + s]; f = pos[(long)c * S_TOTAL + s]; }
        t1[ty + i * 8][tx] = a;
        t2[ty + i * 8][tx] = f;
    }
    __syncthreads();
    #pragma unroll
    for (int i = 0; i < 4; i++) {
        int s = s0 + ty + i * 8, c = c0 + tx;
        if (s < S_TOTAL) {
            float a = t1[tx][ty + i * 8];
            float f = t2[tx][ty + i * 8];
            srct[(long)s * 256 + c]   = a;
            srcpos[(long)s * 256 + c] = a + f;
        }
    }
}

__global__ void init_qx(const float* __restrict__ qemb, float* __restrict__ qe, float* __restrict__ x)
{
    int r = blockIdx.x, c = threadIdx.x;
    qe[r * 256 + c] = qemb[r * 512 + c];
    x[r * 256 + c]  = qemb[r * 512 + 256 + c];
}

__global__ void detect_mask(const unsigned int* __restrict__ w)
{
    if (threadIdx.x == 0) { g_mask_float = 0; g_mask_byte = 0; }
    __syncthreads();
    int fl = 0, by = 0;
    for (int i = threadIdx.x; i < 65536; i += 256) {
        unsigned int v = w[i];
        if (v == 0x3F800000u) fl = 1;
        else if (v > 1u) by = 1;
    }
    if (fl) atomicOr(&g_mask_float, 1);
    if (by) atomicOr(&g_mask_byte, 1);
}

__global__ void mask_to_bits(const void* __restrict__ mask, unsigned* __restrict__ bits)
{
    int idx = blockIdx.x * 256 + threadIdx.x;
    if (idx >= NQ * SW) return;
    int q = idx / SW, w = idx % SW;
    unsigned out = 0;
    int base = w * 32;
    int fl = g_mask_float, by = g_mask_byte;
    #pragma unroll 4
    for (int j = 0; j < 32; j++) {
        int s = base + j;
        if (s >= S_TOTAL) break;
        long off = (long)q * S_TOTAL + s;
        int blocked;
        if (fl)      blocked = ((const float*)mask)[off] != 0.f;
        else if (by) blocked = ((const unsigned char*)mask)[off] != 0;
        else         blocked = ((const int*)mask)[off] != 0;
        if (!blocked) out |= 1u << j;
    }
    bits[idx] = out;
}

__global__ void copy_out(const float* __restrict__ x, float* __restrict__ out, int n)
{
    int i = blockIdx.x * 256 + threadIdx.x;
    if (i < n) out[i] = x[i];
}

// ------------------------- host driver -------------------------
static inline dim3 gtile(int M, int N, int z, int BM) {
    return dim3((N + 63) / 64, (M + BM - 1) / BM, z);
}

extern "C" void kernel_launch(void* const* d_in, const int* in_sizes, int n_in,
                              void* d_out, int out_size)
{
    const float* srcs    = (const float*)d_in[0];
    const float* pos     = (const float*)d_in[1];
    const float* qemb    = (const float*)d_in[2];
    const void*  mask    = d_in[3];
    const float* sa_in_w = (const float*)d_in[4];
    const float* sa_in_b = (const float*)d_in[5];
    const float* sa_ow   = (const float*)d_in[6];
    const float* sa_ob   = (const float*)d_in[7];
    const float* ca_in_w = (const float*)d_in[8];
    const float* ca_in_b = (const float*)d_in[9];
    const float* ca_ow   = (const float*)d_in[10];
    const float* ca_ob   = (const float*)d_in[11];
    const float* ln1w = (const float*)d_in[12];
    const float* ln1b = (const float*)d_in[13];
    const float* ln2w = (const float*)d_in[14];
    const float* ln2b = (const float*)d_in[15];
    const float* ln3w = (const float*)d_in[16];
    const float* ln3b = (const float*)d_in[17];
    const float* ff1w = (const float*)d_in[18];
    const float* ff1b = (const float*)d_in[19];
    const float* ff2w = (const float*)d_in[20];
    const float* ff2b = (const float*)d_in[21];

    float *srct, *srcpos, *kvall, *opart, *x, *qe, *t2, *qkv, *qb, *sas, *ao, *ffh;
    float2* mspart; unsigned* mbits;
    cudaGetSymbolAddress((void**)&srct, g_srct);
    cudaGetSymbolAddress((void**)&srcpos, g_srcpos);
    cudaGetSymbolAddress((void**)&mbits, g_mbits);
    cudaGetSymbolAddress((void**)&kvall, g_kvall);
    cudaGetSymbolAddress((void**)&opart, g_opart);
    cudaGetSymbolAddress((void**)&mspart, g_mspart);
    cudaGetSymbolAddress((void**)&x, g_x);
    cudaGetSymbolAddress((void**)&qe, g_qe);
    cudaGetSymbolAddress((void**)&t2, g_t2);
    cudaGetSymbolAddress((void**)&qkv, g_qkv);
    cudaGetSymbolAddress((void**)&qb, g_qb);
    cudaGetSymbolAddress((void**)&sas, g_sas);
    cudaGetSymbolAddress((void**)&ao, g_ao);
    cudaGetSymbolAddress((void**)&ffh, g_ffh);

    const float scale = 0.17677669529663687f;  // 32^-0.5
    const int C = C_MODEL, S = S_TOTAL;
    const int BIG = 1 << 30;

    // preprocessing
    prep_src<<<dim3((S + 31) / 32, C / 32), dim3(32, 8)>>>(srcs, pos, srct, srcpos);
    init_qx<<<NQ, 256>>>(qemb, qe, x);
    detect_mask<<<1, 256>>>((const unsigned int*)mask);
    mask_to_bits<<<(NQ * SW + 255) / 256, 256>>>(mask, mbits);

    // all-layer K/V projection: [l][S][512]; K cols from srcpos, V cols from srct
    tfgemm<128><<<gtile(S, 512, NLAYERS, 128), 256>>>(
        srcpos, srct, nullptr, 256,
        ca_in_w + C * C, ca_in_b + C, kvall,
        S, 512, C, C, C, 512,
        0L, (long)3 * C * C, (long)3 * C, (long)S * 512,
        1.f, 0, 0);

    for (int l = 0; l < NLAYERS; l++) {
        const float* saw = sa_in_w + (long)l * 3 * C * C;
        const float* sab = sa_in_b + (long)l * 3 * C;
        const float* caw = ca_in_w + (long)l * 3 * C * C;
        const float* cab = ca_in_b + (long)l * 3 * C;
        const float* kvl = kvall + (long)l * S * 512;

        // ---- self attention ----
        // fused QKV: cols 0-511 use x+qe (q,k), 512-767 use x (v); scale q cols
        tfgemm<64><<<gtile(NQ, 3 * C, 1, 64), 256>>>(
            x, x, qe, 512, saw, sab, qkv,
            NQ, 3 * C, C, C, C, 3 * C, 0, 0, 0, 0, scale, C, 0);
        // scores: per-head q @ k^T
        tfgemm<64><<<gtile(NQ, NQ, NHEADS, 64), 256>>>(
            qkv, nullptr, nullptr, BIG, qkv + C, nullptr, sas,
            NQ, NQ, DHEAD, 3 * C, 3 * C, NQ, 32L, 32L, 0, (long)NQ * NQ, 1.f, 0, 0);
        softmax_rows<<<NHEADS * NQ, 256>>>(sas, NQ);
        gemm_nn<<<dim3(1, (NQ + 31) / 32, NHEADS), 256>>>(sas, qkv + 2 * C, ao,
            NQ, DHEAD, NQ, NQ, 3 * C, C, (long)NQ * NQ, 32L, 32L);
        tfgemm<64><<<gtile(NQ, C, 1, 64), 256>>>(
            ao, nullptr, nullptr, BIG, sa_ow + (long)l * C * C, sa_ob + (long)l * C, t2,
            NQ, C, C, C, C, C, 0, 0, 0, 0, 1.f, 0, 0);
        residual_ln<<<NQ, 256>>>(x, t2, ln2w + (long)l * C, ln2b + (long)l * C);

        // ---- cross attention (flash) ----
        tfgemm<64><<<gtile(NQ, C, 1, 64), 256>>>(
            x, nullptr, qe, BIG, caw, cab, qb,
            NQ, C, C, C, C, C, 0, 0, 0, 0, scale, C, 0);
        flash_ca<<<dim3(NCHUNK, NHEADS), 160>>>(qb, kvl, mbits, opart, mspart);
        ca_combine<<<(NHEADS * NQ + 255) / 256, 256>>>(opart, mspart, ao);
        tfgemm<64><<<gtile(NQ, C, 1, 64), 256>>>(
            ao, nullptr, nullptr, BIG, ca_ow + (long)l * C * C, ca_ob + (long)l * C, t2,
            NQ, C, C, C, C, C, 0, 0, 0, 0, 1.f, 0, 0);
        residual_ln<<<NQ, 256>>>(x, t2, ln1w + (long)l * C, ln1b + (long)l * C);

        // ---- FFN ----
        tfgemm<64><<<gtile(NQ, DFF, 1, 64), 256>>>(
            x, nullptr, nullptr, BIG, ff1w + (long)l * DFF * C, ff1b + (long)l * DFF, ffh,
            NQ, DFF, C, C, C, DFF, 0, 0, 0, 0, 1.f, 0, 1);
        tfgemm<64><<<gtile(NQ, C, 1, 64), 256>>>(
            ffh, nullptr, nullptr, BIG, ff2w + (long)l * C * DFF, ff2b + (long)l * C, t2,
            NQ, C, DFF, DFF, DFF, C, 0, 0, 0, 0, 1.f, 0, 0);
        residual_ln<<<NQ, 256>>>(x, t2, ln3w + (long)l * C, ln3b + (long)l * C);
    }

    copy_out<<<(NQ * C + 255) / 256, 256>>>(x, (float*)d_out, NQ * C);
}